// round 15
// baseline (speedup 1.0000x reference)
#include <cuda_runtime.h>
#include <cstdint>

#define D         32000
#define D4        8000
#define ROW_BYTES 128000
#define THREADS   1024
#define NV4       8
#define NE        32
#define MAX_ITER  100
#define TOL       1e-5f
#define HI_OFFSET 1.9888196601125011f   // -gp(1/32000) = 2 - 2/sqrt(32000)
#define NEG_BIG   -1e30f
#define ROWS      4096
#define FIXS      2097152.0f            // 2^21
#define INVFIXS   4.76837158203125e-7f  // 2^-21

__device__ __forceinline__ uint32_t smem_u32(const void* p) {
    uint32_t a;
    asm("{ .reg .u64 t; cvta.to.shared.u64 t, %1; cvt.u32.u64 %0, t; }"
        : "=r"(a) : "l"(p));
    return a;
}

__device__ __forceinline__ void mbar_init(uint32_t mbar, uint32_t count) {
    asm volatile("mbarrier.init.shared.b64 [%0], %1;" :: "r"(mbar), "r"(count) : "memory");
}

__device__ __forceinline__ void tma_prefetch_row(uint32_t dst_smem, const float* src,
                                                 uint32_t mbar) {
    asm volatile("mbarrier.arrive.expect_tx.shared.b64 _, [%0], %1;"
                 :: "r"(mbar), "r"((uint32_t)ROW_BYTES) : "memory");
    asm volatile("cp.async.bulk.shared::cta.global.mbarrier::complete_tx::bytes "
                 "[%0], [%1], %2, [%3];"
                 :: "r"(dst_smem), "l"(src), "r"((uint32_t)ROW_BYTES), "r"(mbar)
                 : "memory");
}

__device__ __forceinline__ void mbar_wait(uint32_t mbar, uint32_t phase) {
    asm volatile(
        "{\n\t"
        ".reg .pred P;\n\t"
        "W%=:\n\t"
        "mbarrier.try_wait.parity.acquire.cta.shared::cta.b64 P, [%0], %1, 0x989680;\n\t"
        "@!P bra W%=;\n\t"
        "}"
        :: "r"(mbar), "r"(phase) : "memory");
}

// HW warp reductions (sm_80+): single REDUX instruction
__device__ __forceinline__ int redux_add_s32(int v) {
    int r;
    asm volatile("redux.sync.add.s32 %0, %1, 0xffffffff;" : "=r"(r) : "r"(v));
    return r;
}
__device__ __forceinline__ unsigned redux_max_u32(unsigned v) {
    unsigned r;
    asm volatile("redux.sync.max.u32 %0, %1, 0xffffffff;" : "=r"(r) : "r"(v));
    return r;
}

__device__ __forceinline__ float warp_sum(float v) {
#pragma unroll
    for (int o = 16; o; o >>= 1) v += __shfl_xor_sync(0xffffffffu, v, o);
    return v;
}

// monotonic float <-> u32 key (no NaNs in data)
__device__ __forceinline__ unsigned fkey(float x) {
    unsigned u = __float_as_uint(x);
    return (u & 0x80000000u) ? ~u : (u | 0x80000000u);
}
__device__ __forceinline__ float funkey(unsigned k) {
    unsigned u = (k & 0x80000000u) ? (k & 0x7fffffffu) : ~k;
    return __uint_as_float(u);
}

__global__ void __launch_bounds__(THREADS, 1)
tsallis_secant_kernel(const float* __restrict__ X, float* __restrict__ Y) {
    extern __shared__ float buf[];          // D floats: TMA staging buffer
    __shared__ int   ired[2][32];           // double-buffered fixed-point partials
    __shared__ int2  ired2[32];
    __shared__ unsigned mred[32];
    __shared__ float fred[2][32];           // float scratch (rare fallback path)
    __shared__ __align__(8) uint64_t mbar_storage;

    const int tid  = threadIdx.x;
    const int lane = tid & 31;
    const int wid  = tid >> 5;

    const uint32_t mbar    = smem_u32(&mbar_storage);
    const uint32_t buf_u32 = smem_u32(buf);

    if (tid == 0) mbar_init(mbar, 1);
    __syncthreads();

    int rb = 0;  // reduction buffer toggle (uniform across threads)

    // fast block sum via integer REDUX (deterministic fixed point)
    auto block_sum_fix = [&](float s) -> float {
        int si = __float2int_rn(s * FIXS);
        si = redux_add_s32(si);
        if (lane == 0) ired[rb][wid] = si;
        __syncthreads();
        int t = redux_add_s32(ired[rb][lane]);
        rb ^= 1;
        return (float)t * INVFIXS;
    };

    // float shfl block sum (exact path for rare left-overshoot evals)
    auto block_sum_f = [&](float s) -> float {
        s = warp_sum(s);
        if (lane == 0) fred[rb][wid] = s;
        __syncthreads();
        float t = warp_sum(fred[rb][lane]);
        rb ^= 1;
        return t;
    };

    int row = blockIdx.x;
    const int stride = gridDim.x;

    if (tid == 0 && row < ROWS) {
        tma_prefetch_row(buf_u32, X + (size_t)row * D, mbar);
    }
    uint32_t phase = 0;

    for (; row < ROWS; row += stride) {
        mbar_wait(mbar, phase);
        phase ^= 1;

        // ---- SMEM -> registers, fused local max ----
        float xv[NE];
        float m = NEG_BIG;
        const float4* b4 = reinterpret_cast<const float4*>(buf);
#pragma unroll
        for (int k = 0; k < NV4; k++) {
            const int i4 = tid + k * THREADS;
            if (k < NV4 - 1 || i4 < D4) {
                float4 v = b4[i4];
                xv[4 * k + 0] = v.x;
                xv[4 * k + 1] = v.y;
                xv[4 * k + 2] = v.z;
                xv[4 * k + 3] = v.w;
            } else {
                xv[4 * k + 0] = NEG_BIG;
                xv[4 * k + 1] = NEG_BIG;
                xv[4 * k + 2] = NEG_BIG;
                xv[4 * k + 3] = NEG_BIG;
            }
        }
#pragma unroll
        for (int k = 0; k < NE; k++) m = fmaxf(m, xv[k]);

        __syncthreads();   // B1: buf consumed; also fences prev-row scratch

        // ---- kick prefetch of next row (overlaps everything below) ----
        const int nrow = row + stride;
        if (tid == 0 && nrow < ROWS) {
            tma_prefetch_row(buf_u32, X + (size_t)nrow * D, mbar);
        }

        // ---- block max via REDUX.max.u32 on monotonic keys ----
        unsigned mk = redux_max_u32(fkey(m));
        if (lane == 0) mred[wid] = mk;
        __syncthreads();   // B2
        const float max_val = funkey(redux_max_u32(mred[lane]));

        // ---- per-thread register pack of active set {x > max-2} ----
        const float thr = max_val - 2.0f;
        float pk0 = NEG_BIG, pk1 = NEG_BIG, pk2 = NEG_BIG, pk3 = NEG_BIG;
        int c = 0;
#pragma unroll
        for (int k = 0; k < NE; k++) {
            float x = xv[k];
            if (x > thr) {
                if      (c == 0) pk0 = x;
                else if (c == 1) pk1 = x;
                else if (c == 2) pk2 = x;
                else if (c == 3) pk3 = x;
                c++;
            }
        }
        const bool full = (c > 4);          // rare per-thread fallback

        // full-row partial sum for one tau (this thread's 32 elements)
        auto part_full = [&](float c2) -> float {
            float a0 = 0.f, a1 = 0.f, a2 = 0.f, a3 = 0.f;
#pragma unroll
            for (int k = 0; k < NE; k += 4) {
                float v0 = fmaxf(fmaf(xv[k + 0], 0.5f, c2), 0.0f);
                float v1 = fmaxf(fmaf(xv[k + 1], 0.5f, c2), 0.0f);
                float v2 = fmaxf(fmaf(xv[k + 2], 0.5f, c2), 0.0f);
                float v3 = fmaxf(fmaf(xv[k + 3], 0.5f, c2), 0.0f);
                a0 = fmaf(v0, v0, a0);
                a1 = fmaf(v1, v1, a1);
                a2 = fmaf(v2, v2, a2);
                a3 = fmaf(v3, v3, a3);
            }
            return (a0 + a1) + (a2 + a3);
        };

        // packed partial (valid when tau >= max_val and !full)
        auto part_packed = [&](float c2) -> float {
            float v0 = fmaxf(fmaf(pk0, 0.5f, c2), 0.0f);
            float v1 = fmaxf(fmaf(pk1, 0.5f, c2), 0.0f);
            float v2 = fmaxf(fmaf(pk2, 0.5f, c2), 0.0f);
            float v3 = fmaxf(fmaf(pk3, 0.5f, c2), 0.0f);
            return fmaf(v0, v0, fmaf(v1, v1, fmaf(v2, v2, v3 * v3)));
        };

        // exact f(tau) for ANY tau (uniform branch on tau)
        auto eval = [&](float tau) -> float {
            const float c2 = fmaf(tau, -0.5f, 1.0f);
            if (tau >= max_val) {
                float a = full ? part_full(c2) : part_packed(c2);
                return block_sum_fix(a);        // fast REDUX path
            } else {
                return block_sum_f(part_full(c2)); // rare exact float path
            }
        };

        // ---- fused initial evals (both taus >= max_val by construction) ----
        float lo = max_val;                 // gp(1.0) = 0
        float hi = max_val + HI_OFFSET;
        float f_lo, f_hi;
        {
            const float cl = fmaf(lo, -0.5f, 1.0f);
            const float ch = fmaf(hi, -0.5f, 1.0f);
            float a, b;
            if (full) { a = part_full(cl); b = part_full(ch); }
            else      { a = part_packed(cl); b = part_packed(ch); }
            int sa = redux_add_s32(__float2int_rn(a * FIXS));
            int sb = redux_add_s32(__float2int_rn(b * FIXS));
            if (lane == 0) ired2[wid] = make_int2(sa, sb);
            __syncthreads();   // B3
            int2 t = ired2[lane];
            f_lo = (float)redux_add_s32(t.x) * INVFIXS - 1.0f;
            f_hi = (float)redux_add_s32(t.y) * INVFIXS - 1.0f;
        }

        // ---- secant with early exit ----
#pragma unroll 1
        for (int it = 0; it < MAX_ITER; it++) {
            const float diff = f_lo - f_hi;
            if (diff * diff < TOL) break;
            const float tau = (lo * f_hi - hi * f_lo) / (f_hi - f_lo);
            lo = hi;
            f_lo = f_hi;
            hi = tau;
            f_hi = eval(hi) - 1.0f;
        }
        const float tau_final = hi;

        // ---- write p(X - tau_final) with streaming stores ----
        float4* y4 = reinterpret_cast<float4*>(Y) + (size_t)row * D4;
        const float c2 = fmaf(tau_final, -0.5f, 1.0f);
#pragma unroll
        for (int k = 0; k < NV4; k++) {
            const int i4 = tid + k * THREADS;
            if (k < NV4 - 1 || i4 < D4) {
                float v0 = fmaxf(fmaf(xv[4 * k + 0], 0.5f, c2), 0.0f);
                float v1 = fmaxf(fmaf(xv[4 * k + 1], 0.5f, c2), 0.0f);
                float v2 = fmaxf(fmaf(xv[4 * k + 2], 0.5f, c2), 0.0f);
                float v3 = fmaxf(fmaf(xv[4 * k + 3], 0.5f, c2), 0.0f);
                float4 r;
                r.x = v0 * v0;
                r.y = v1 * v1;
                r.z = v2 * v2;
                r.w = v3 * v3;
                __stcs(&y4[i4], r);
            }
        }
        // no trailing barrier: every next-row scratch write is preceded by
        // >=1 __syncthreads (B1 for buf/TMA, B2 for mred, B3+ for ired/ired2)
        // after this row's last read of the same slot.
    }
}

extern "C" void kernel_launch(void* const* d_in, const int* in_sizes, int n_in,
                              void* d_out, int out_size) {
    const float* X = (const float*)d_in[0];
    float* Y = (float*)d_out;

    static int n_sm = 0;
    if (n_sm == 0) {
        cudaDeviceGetAttribute(&n_sm, cudaDevAttrMultiProcessorCount, 0);
        cudaFuncSetAttribute(tsallis_secant_kernel,
                             cudaFuncAttributeMaxDynamicSharedMemorySize,
                             ROW_BYTES);
    }
    tsallis_secant_kernel<<<n_sm, THREADS, ROW_BYTES>>>(X, Y);
}

// round 16
// speedup vs baseline: 1.0112x; 1.0112x over previous
#include <cuda_runtime.h>
#include <cstdint>

#define D         32000
#define D4        8000
#define ROW_BYTES 128000
#define HALF_A_BYTES 65536              // slots k=0..3  (float4 idx 0..4095)
#define HALF_B_BYTES 62464              // slots k=4..7  (float4 idx 4096..7999)
#define THREADS   1024
#define NV4       8
#define NE        32
#define MAX_ITER  100
#define TOL       1e-5f
#define HI_OFFSET 1.9888196601125011f   // -gp(1/32000) = 2 - 2/sqrt(32000)
#define NEG_BIG   -1e30f
#define ROWS      4096
#define FIXS      2097152.0f            // 2^21
#define INVFIXS   4.76837158203125e-7f  // 2^-21

__device__ __forceinline__ uint32_t smem_u32(const void* p) {
    uint32_t a;
    asm("{ .reg .u64 t; cvta.to.shared.u64 t, %1; cvt.u32.u64 %0, t; }"
        : "=r"(a) : "l"(p));
    return a;
}

__device__ __forceinline__ void mbar_init(uint32_t mbar, uint32_t count) {
    asm volatile("mbarrier.init.shared.b64 [%0], %1;" :: "r"(mbar), "r"(count) : "memory");
}

__device__ __forceinline__ void tma_chunk(uint32_t dst_smem, const float* src,
                                          uint32_t bytes, uint32_t mbar) {
    asm volatile("mbarrier.arrive.expect_tx.shared.b64 _, [%0], %1;"
                 :: "r"(mbar), "r"(bytes) : "memory");
    asm volatile("cp.async.bulk.shared::cta.global.mbarrier::complete_tx::bytes "
                 "[%0], [%1], %2, [%3];"
                 :: "r"(dst_smem), "l"(src), "r"(bytes), "r"(mbar)
                 : "memory");
}

__device__ __forceinline__ void mbar_wait(uint32_t mbar, uint32_t phase) {
    asm volatile(
        "{\n\t"
        ".reg .pred P;\n\t"
        "W%=:\n\t"
        "mbarrier.try_wait.parity.acquire.cta.shared::cta.b64 P, [%0], %1, 0x989680;\n\t"
        "@!P bra W%=;\n\t"
        "}"
        :: "r"(mbar), "r"(phase) : "memory");
}

// HW warp reductions (sm_80+): single REDUX instruction
__device__ __forceinline__ int redux_add_s32(int v) {
    int r;
    asm volatile("redux.sync.add.s32 %0, %1, 0xffffffff;" : "=r"(r) : "r"(v));
    return r;
}
__device__ __forceinline__ unsigned redux_max_u32(unsigned v) {
    unsigned r;
    asm volatile("redux.sync.max.u32 %0, %1, 0xffffffff;" : "=r"(r) : "r"(v));
    return r;
}

__device__ __forceinline__ float warp_sum(float v) {
#pragma unroll
    for (int o = 16; o; o >>= 1) v += __shfl_xor_sync(0xffffffffu, v, o);
    return v;
}

// monotonic float <-> u32 key (no NaNs in data)
__device__ __forceinline__ unsigned fkey(float x) {
    unsigned u = __float_as_uint(x);
    return (u & 0x80000000u) ? ~u : (u | 0x80000000u);
}
__device__ __forceinline__ float funkey(unsigned k) {
    unsigned u = (k & 0x80000000u) ? (k & 0x7fffffffu) : ~k;
    return __uint_as_float(u);
}

__global__ void __launch_bounds__(THREADS, 1)
tsallis_secant_kernel(const float* __restrict__ X, float* __restrict__ Y) {
    extern __shared__ float buf[];          // D floats: TMA staging buffer
    __shared__ int   ired[2][32];           // double-buffered fixed-point partials
    __shared__ int2  ired2[32];
    __shared__ unsigned mred[32];
    __shared__ float fred[2][32];           // float scratch (rare fallback path)
    __shared__ __align__(8) uint64_t mbar_storage[2];

    const int tid  = threadIdx.x;
    const int lane = tid & 31;
    const int wid  = tid >> 5;

    const uint32_t mbarA   = smem_u32(&mbar_storage[0]);
    const uint32_t mbarB   = smem_u32(&mbar_storage[1]);
    const uint32_t buf_u32 = smem_u32(buf);

    if (tid == 0) { mbar_init(mbarA, 1); mbar_init(mbarB, 1); }
    __syncthreads();

    int rb = 0;  // reduction buffer toggle (uniform across threads)

    // fast block sum via integer REDUX (deterministic fixed point)
    auto block_sum_fix = [&](float s) -> float {
        int si = __float2int_rn(s * FIXS);
        si = redux_add_s32(si);
        if (lane == 0) ired[rb][wid] = si;
        __syncthreads();
        int t = redux_add_s32(ired[rb][lane]);
        rb ^= 1;
        return (float)t * INVFIXS;
    };

    // float shfl block sum (exact path for rare left-overshoot evals)
    auto block_sum_f = [&](float s) -> float {
        s = warp_sum(s);
        if (lane == 0) fred[rb][wid] = s;
        __syncthreads();
        float t = warp_sum(fred[rb][lane]);
        rb ^= 1;
        return t;
    };

    int row = blockIdx.x;
    const int stride = gridDim.x;

    if (tid == 0 && row < ROWS) {
        const float* src = X + (size_t)row * D;
        tma_chunk(buf_u32, src, HALF_A_BYTES, mbarA);
        tma_chunk(buf_u32 + HALF_A_BYTES,
                  src + HALF_A_BYTES / 4, HALF_B_BYTES, mbarB);
    }
    uint32_t phase = 0;

    for (; row < ROWS; row += stride) {
        float xv[NE];
        float m = NEG_BIG;
        const float4* b4 = reinterpret_cast<const float4*>(buf);

        // ---- half A: wait + copy (overlaps half B's in-flight DMA) ----
        mbar_wait(mbarA, phase);
#pragma unroll
        for (int k = 0; k < 4; k++) {
            const int i4 = tid + k * THREADS;          // < 4096: all in half A
            float4 v = b4[i4];
            xv[4 * k + 0] = v.x;
            xv[4 * k + 1] = v.y;
            xv[4 * k + 2] = v.z;
            xv[4 * k + 3] = v.w;
        }

        // ---- half B: wait + copy ----
        mbar_wait(mbarB, phase);
        phase ^= 1;
#pragma unroll
        for (int k = 4; k < NV4; k++) {
            const int i4 = tid + k * THREADS;
            if (k < NV4 - 1 || i4 < D4) {
                float4 v = b4[i4];
                xv[4 * k + 0] = v.x;
                xv[4 * k + 1] = v.y;
                xv[4 * k + 2] = v.z;
                xv[4 * k + 3] = v.w;
            } else {
                xv[4 * k + 0] = NEG_BIG;
                xv[4 * k + 1] = NEG_BIG;
                xv[4 * k + 2] = NEG_BIG;
                xv[4 * k + 3] = NEG_BIG;
            }
        }
#pragma unroll
        for (int k = 0; k < NE; k++) m = fmaxf(m, xv[k]);

        __syncthreads();   // B1: buf consumed; also fences prev-row scratch

        // ---- kick both prefetches for the next row ----
        const int nrow = row + stride;
        if (tid == 0 && nrow < ROWS) {
            const float* src = X + (size_t)nrow * D;
            tma_chunk(buf_u32, src, HALF_A_BYTES, mbarA);
            tma_chunk(buf_u32 + HALF_A_BYTES,
                      src + HALF_A_BYTES / 4, HALF_B_BYTES, mbarB);
        }

        // ---- block max via REDUX.max.u32 on monotonic keys ----
        unsigned mk = redux_max_u32(fkey(m));
        if (lane == 0) mred[wid] = mk;
        __syncthreads();   // B2
        const float max_val = funkey(redux_max_u32(mred[lane]));

        // ---- per-thread register pack of active set {x > max-2} ----
        const float thr = max_val - 2.0f;
        float pk0 = NEG_BIG, pk1 = NEG_BIG, pk2 = NEG_BIG, pk3 = NEG_BIG;
        int c = 0;
#pragma unroll
        for (int k = 0; k < NE; k++) {
            float x = xv[k];
            if (x > thr) {
                if      (c == 0) pk0 = x;
                else if (c == 1) pk1 = x;
                else if (c == 2) pk2 = x;
                else if (c == 3) pk3 = x;
                c++;
            }
        }
        const bool full = (c > 4);          // rare per-thread fallback

        // full-row partial sum for one tau (this thread's 32 elements)
        auto part_full = [&](float c2) -> float {
            float a0 = 0.f, a1 = 0.f, a2 = 0.f, a3 = 0.f;
#pragma unroll
            for (int k = 0; k < NE; k += 4) {
                float v0 = fmaxf(fmaf(xv[k + 0], 0.5f, c2), 0.0f);
                float v1 = fmaxf(fmaf(xv[k + 1], 0.5f, c2), 0.0f);
                float v2 = fmaxf(fmaf(xv[k + 2], 0.5f, c2), 0.0f);
                float v3 = fmaxf(fmaf(xv[k + 3], 0.5f, c2), 0.0f);
                a0 = fmaf(v0, v0, a0);
                a1 = fmaf(v1, v1, a1);
                a2 = fmaf(v2, v2, a2);
                a3 = fmaf(v3, v3, a3);
            }
            return (a0 + a1) + (a2 + a3);
        };

        // packed partial (valid when tau >= max_val and !full)
        auto part_packed = [&](float c2) -> float {
            float v0 = fmaxf(fmaf(pk0, 0.5f, c2), 0.0f);
            float v1 = fmaxf(fmaf(pk1, 0.5f, c2), 0.0f);
            float v2 = fmaxf(fmaf(pk2, 0.5f, c2), 0.0f);
            float v3 = fmaxf(fmaf(pk3, 0.5f, c2), 0.0f);
            return fmaf(v0, v0, fmaf(v1, v1, fmaf(v2, v2, v3 * v3)));
        };

        // exact f(tau) for ANY tau (uniform branch on tau)
        auto eval = [&](float tau) -> float {
            const float c2 = fmaf(tau, -0.5f, 1.0f);
            if (tau >= max_val) {
                float a = full ? part_full(c2) : part_packed(c2);
                return block_sum_fix(a);        // fast REDUX path
            } else {
                return block_sum_f(part_full(c2)); // rare exact float path
            }
        };

        // ---- fused initial evals (both taus >= max_val by construction) ----
        float lo = max_val;                 // gp(1.0) = 0
        float hi = max_val + HI_OFFSET;
        float f_lo, f_hi;
        {
            const float cl = fmaf(lo, -0.5f, 1.0f);
            const float ch = fmaf(hi, -0.5f, 1.0f);
            float a, b;
            if (full) { a = part_full(cl); b = part_full(ch); }
            else      { a = part_packed(cl); b = part_packed(ch); }
            int sa = redux_add_s32(__float2int_rn(a * FIXS));
            int sb = redux_add_s32(__float2int_rn(b * FIXS));
            if (lane == 0) ired2[wid] = make_int2(sa, sb);
            __syncthreads();   // B3
            int2 t = ired2[lane];
            f_lo = (float)redux_add_s32(t.x) * INVFIXS - 1.0f;
            f_hi = (float)redux_add_s32(t.y) * INVFIXS - 1.0f;
        }

        // ---- secant with early exit ----
#pragma unroll 1
        for (int it = 0; it < MAX_ITER; it++) {
            const float diff = f_lo - f_hi;
            if (diff * diff < TOL) break;
            const float tau = (lo * f_hi - hi * f_lo) / (f_hi - f_lo);
            lo = hi;
            f_lo = f_hi;
            hi = tau;
            f_hi = eval(hi) - 1.0f;
        }
        const float tau_final = hi;

        // ---- write p(X - tau_final) with streaming stores ----
        float4* y4 = reinterpret_cast<float4*>(Y) + (size_t)row * D4;
        const float c2 = fmaf(tau_final, -0.5f, 1.0f);
#pragma unroll
        for (int k = 0; k < NV4; k++) {
            const int i4 = tid + k * THREADS;
            if (k < NV4 - 1 || i4 < D4) {
                float v0 = fmaxf(fmaf(xv[4 * k + 0], 0.5f, c2), 0.0f);
                float v1 = fmaxf(fmaf(xv[4 * k + 1], 0.5f, c2), 0.0f);
                float v2 = fmaxf(fmaf(xv[4 * k + 2], 0.5f, c2), 0.0f);
                float v3 = fmaxf(fmaf(xv[4 * k + 3], 0.5f, c2), 0.0f);
                float4 r;
                r.x = v0 * v0;
                r.y = v1 * v1;
                r.z = v2 * v2;
                r.w = v3 * v3;
                __stcs(&y4[i4], r);
            }
        }
        // no trailing barrier: every next-row scratch write is preceded by
        // >=1 __syncthreads (B1 for buf/TMA, B2 for mred, B3+ for ired/ired2)
        // after this row's last read of the same slot.
    }
}

extern "C" void kernel_launch(void* const* d_in, const int* in_sizes, int n_in,
                              void* d_out, int out_size) {
    const float* X = (const float*)d_in[0];
    float* Y = (float*)d_out;

    static int n_sm = 0;
    if (n_sm == 0) {
        cudaDeviceGetAttribute(&n_sm, cudaDevAttrMultiProcessorCount, 0);
        cudaFuncSetAttribute(tsallis_secant_kernel,
                             cudaFuncAttributeMaxDynamicSharedMemorySize,
                             ROW_BYTES);
    }
    tsallis_secant_kernel<<<n_sm, THREADS, ROW_BYTES>>>(X, Y);
}

// round 17
// speedup vs baseline: 1.0368x; 1.0253x over previous
#include <cuda_runtime.h>
#include <cstdint>

#define D         32000
#define D4        8000
#define ROW_BYTES 128000
#define CHUNK_BYTES   32768             // slots 2k,2k+1 (2048 float4)
#define CHUNK3_BYTES  29696             // slots 6,7: float4 idx 6144..7999
#define THREADS   1024
#define NV4       8
#define NE        32
#define MAX_ITER  100
#define TOL       1e-5f
#define HI_OFFSET 1.9888196601125011f   // -gp(1/32000) = 2 - 2/sqrt(32000)
#define NEG_BIG   -1e30f
#define ROWS      4096
#define FIXS      2097152.0f            // 2^21
#define INVFIXS   4.76837158203125e-7f  // 2^-21

__device__ __forceinline__ uint32_t smem_u32(const void* p) {
    uint32_t a;
    asm("{ .reg .u64 t; cvta.to.shared.u64 t, %1; cvt.u32.u64 %0, t; }"
        : "=r"(a) : "l"(p));
    return a;
}

__device__ __forceinline__ void mbar_init(uint32_t mbar, uint32_t count) {
    asm volatile("mbarrier.init.shared.b64 [%0], %1;" :: "r"(mbar), "r"(count) : "memory");
}

__device__ __forceinline__ void tma_chunk(uint32_t dst_smem, const float* src,
                                          uint32_t bytes, uint32_t mbar) {
    asm volatile("mbarrier.arrive.expect_tx.shared.b64 _, [%0], %1;"
                 :: "r"(mbar), "r"(bytes) : "memory");
    asm volatile("cp.async.bulk.shared::cta.global.mbarrier::complete_tx::bytes "
                 "[%0], [%1], %2, [%3];"
                 :: "r"(dst_smem), "l"(src), "r"(bytes), "r"(mbar)
                 : "memory");
}

__device__ __forceinline__ void mbar_wait(uint32_t mbar, uint32_t phase) {
    asm volatile(
        "{\n\t"
        ".reg .pred P;\n\t"
        "W%=:\n\t"
        "mbarrier.try_wait.parity.acquire.cta.shared::cta.b64 P, [%0], %1, 0x989680;\n\t"
        "@!P bra W%=;\n\t"
        "}"
        :: "r"(mbar), "r"(phase) : "memory");
}

// HW warp reductions (sm_80+): single REDUX instruction
__device__ __forceinline__ int redux_add_s32(int v) {
    int r;
    asm volatile("redux.sync.add.s32 %0, %1, 0xffffffff;" : "=r"(r) : "r"(v));
    return r;
}
__device__ __forceinline__ unsigned redux_max_u32(unsigned v) {
    unsigned r;
    asm volatile("redux.sync.max.u32 %0, %1, 0xffffffff;" : "=r"(r) : "r"(v));
    return r;
}

__device__ __forceinline__ float warp_sum(float v) {
#pragma unroll
    for (int o = 16; o; o >>= 1) v += __shfl_xor_sync(0xffffffffu, v, o);
    return v;
}

// monotonic float <-> u32 key (no NaNs in data)
__device__ __forceinline__ unsigned fkey(float x) {
    unsigned u = __float_as_uint(x);
    return (u & 0x80000000u) ? ~u : (u | 0x80000000u);
}
__device__ __forceinline__ float funkey(unsigned k) {
    unsigned u = (k & 0x80000000u) ? (k & 0x7fffffffu) : ~k;
    return __uint_as_float(u);
}

__global__ void __launch_bounds__(THREADS, 1)
tsallis_secant_kernel(const float* __restrict__ X, float* __restrict__ Y) {
    extern __shared__ float buf[];          // D floats: TMA staging buffer
    __shared__ int   ired[2][32];           // double-buffered fixed-point partials
    __shared__ int2  ired2[32];
    __shared__ unsigned mred[32];
    __shared__ float fred[2][32];           // float scratch (rare fallback path)
    __shared__ __align__(8) uint64_t mbar_storage[4];

    const int tid  = threadIdx.x;
    const int lane = tid & 31;
    const int wid  = tid >> 5;

    uint32_t mbarC[4];
#pragma unroll
    for (int i = 0; i < 4; i++) mbarC[i] = smem_u32(&mbar_storage[i]);
    const uint32_t buf_u32 = smem_u32(buf);

    if (tid == 0) {
#pragma unroll
        for (int i = 0; i < 4; i++) mbar_init(mbarC[i], 1);
    }
    __syncthreads();

    int rb = 0;  // reduction buffer toggle (uniform across threads)

    // fast block sum via integer REDUX (deterministic fixed point)
    auto block_sum_fix = [&](float s) -> float {
        int si = __float2int_rn(s * FIXS);
        si = redux_add_s32(si);
        if (lane == 0) ired[rb][wid] = si;
        __syncthreads();
        int t = redux_add_s32(ired[rb][lane]);
        rb ^= 1;
        return (float)t * INVFIXS;
    };

    // float shfl block sum (exact path for rare left-overshoot evals)
    auto block_sum_f = [&](float s) -> float {
        s = warp_sum(s);
        if (lane == 0) fred[rb][wid] = s;
        __syncthreads();
        float t = warp_sum(fred[rb][lane]);
        rb ^= 1;
        return t;
    };

    // issue all 4 chunk prefetches for one row (tid 0 only)
    auto prefetch_row = [&](int r) {
        const float* src = X + (size_t)r * D;
#pragma unroll
        for (int i = 0; i < 4; i++) {
            const uint32_t off = i * CHUNK_BYTES;
            const uint32_t bytes = (i < 3) ? CHUNK_BYTES : CHUNK3_BYTES;
            tma_chunk(buf_u32 + off, src + off / 4, bytes, mbarC[i]);
        }
    };

    int row = blockIdx.x;
    const int stride = gridDim.x;

    if (tid == 0 && row < ROWS) prefetch_row(row);
    uint32_t phase = 0;

    for (; row < ROWS; row += stride) {
        float xv[NE];
        const float4* b4 = reinterpret_cast<const float4*>(buf);

        // ---- chunked wait+copy: copy of chunk i overlaps DMA of i+1.. ----
#pragma unroll
        for (int i = 0; i < 4; i++) {
            mbar_wait(mbarC[i], phase);
#pragma unroll
            for (int k = 2 * i; k < 2 * i + 2; k++) {
                const int i4 = tid + k * THREADS;
                if (k < NV4 - 1 || i4 < D4) {
                    float4 v = b4[i4];
                    xv[4 * k + 0] = v.x;
                    xv[4 * k + 1] = v.y;
                    xv[4 * k + 2] = v.z;
                    xv[4 * k + 3] = v.w;
                } else {
                    xv[4 * k + 0] = NEG_BIG;
                    xv[4 * k + 1] = NEG_BIG;
                    xv[4 * k + 2] = NEG_BIG;
                    xv[4 * k + 3] = NEG_BIG;
                }
            }
        }
        phase ^= 1;

        float m = NEG_BIG;
#pragma unroll
        for (int k = 0; k < NE; k++) m = fmaxf(m, xv[k]);

        __syncthreads();   // B1: buf consumed; also fences prev-row scratch

        // ---- kick prefetches for the next row ----
        const int nrow = row + stride;
        if (tid == 0 && nrow < ROWS) prefetch_row(nrow);

        // ---- block max via REDUX.max.u32 on monotonic keys ----
        unsigned mk = redux_max_u32(fkey(m));
        if (lane == 0) mred[wid] = mk;
        __syncthreads();   // B2
        const float max_val = funkey(redux_max_u32(mred[lane]));

        // ---- per-thread register pack of active set {x > max-2} ----
        const float thr = max_val - 2.0f;
        float pk0 = NEG_BIG, pk1 = NEG_BIG, pk2 = NEG_BIG, pk3 = NEG_BIG;
        int c = 0;
#pragma unroll
        for (int k = 0; k < NE; k++) {
            float x = xv[k];
            if (x > thr) {
                if      (c == 0) pk0 = x;
                else if (c == 1) pk1 = x;
                else if (c == 2) pk2 = x;
                else if (c == 3) pk3 = x;
                c++;
            }
        }
        const bool full = (c > 4);          // rare per-thread fallback

        // full-row partial sum for one tau (this thread's 32 elements)
        auto part_full = [&](float c2) -> float {
            float a0 = 0.f, a1 = 0.f, a2 = 0.f, a3 = 0.f;
#pragma unroll
            for (int k = 0; k < NE; k += 4) {
                float v0 = fmaxf(fmaf(xv[k + 0], 0.5f, c2), 0.0f);
                float v1 = fmaxf(fmaf(xv[k + 1], 0.5f, c2), 0.0f);
                float v2 = fmaxf(fmaf(xv[k + 2], 0.5f, c2), 0.0f);
                float v3 = fmaxf(fmaf(xv[k + 3], 0.5f, c2), 0.0f);
                a0 = fmaf(v0, v0, a0);
                a1 = fmaf(v1, v1, a1);
                a2 = fmaf(v2, v2, a2);
                a3 = fmaf(v3, v3, a3);
            }
            return (a0 + a1) + (a2 + a3);
        };

        // packed partial (valid when tau >= max_val and !full)
        auto part_packed = [&](float c2) -> float {
            float v0 = fmaxf(fmaf(pk0, 0.5f, c2), 0.0f);
            float v1 = fmaxf(fmaf(pk1, 0.5f, c2), 0.0f);
            float v2 = fmaxf(fmaf(pk2, 0.5f, c2), 0.0f);
            float v3 = fmaxf(fmaf(pk3, 0.5f, c2), 0.0f);
            return fmaf(v0, v0, fmaf(v1, v1, fmaf(v2, v2, v3 * v3)));
        };

        // exact f(tau) for ANY tau (uniform branch on tau)
        auto eval = [&](float tau) -> float {
            const float c2 = fmaf(tau, -0.5f, 1.0f);
            if (tau >= max_val) {
                float a = full ? part_full(c2) : part_packed(c2);
                return block_sum_fix(a);        // fast REDUX path
            } else {
                return block_sum_f(part_full(c2)); // rare exact float path
            }
        };

        // ---- fused initial evals (both taus >= max_val by construction) ----
        float lo = max_val;                 // gp(1.0) = 0
        float hi = max_val + HI_OFFSET;
        float f_lo, f_hi;
        {
            const float cl = fmaf(lo, -0.5f, 1.0f);
            const float ch = fmaf(hi, -0.5f, 1.0f);
            float a, b;
            if (full) { a = part_full(cl); b = part_full(ch); }
            else      { a = part_packed(cl); b = part_packed(ch); }
            int sa = redux_add_s32(__float2int_rn(a * FIXS));
            int sb = redux_add_s32(__float2int_rn(b * FIXS));
            if (lane == 0) ired2[wid] = make_int2(sa, sb);
            __syncthreads();   // B3
            int2 t = ired2[lane];
            f_lo = (float)redux_add_s32(t.x) * INVFIXS - 1.0f;
            f_hi = (float)redux_add_s32(t.y) * INVFIXS - 1.0f;
        }

        // ---- secant with early exit ----
#pragma unroll 1
        for (int it = 0; it < MAX_ITER; it++) {
            const float diff = f_lo - f_hi;
            if (diff * diff < TOL) break;
            const float tau = (lo * f_hi - hi * f_lo) / (f_hi - f_lo);
            lo = hi;
            f_lo = f_hi;
            hi = tau;
            f_hi = eval(hi) - 1.0f;
        }
        const float tau_final = hi;

        // ---- write p(X - tau_final) with streaming stores ----
        float4* y4 = reinterpret_cast<float4*>(Y) + (size_t)row * D4;
        const float c2 = fmaf(tau_final, -0.5f, 1.0f);
#pragma unroll
        for (int k = 0; k < NV4; k++) {
            const int i4 = tid + k * THREADS;
            if (k < NV4 - 1 || i4 < D4) {
                float v0 = fmaxf(fmaf(xv[4 * k + 0], 0.5f, c2), 0.0f);
                float v1 = fmaxf(fmaf(xv[4 * k + 1], 0.5f, c2), 0.0f);
                float v2 = fmaxf(fmaf(xv[4 * k + 2], 0.5f, c2), 0.0f);
                float v3 = fmaxf(fmaf(xv[4 * k + 3], 0.5f, c2), 0.0f);
                float4 r;
                r.x = v0 * v0;
                r.y = v1 * v1;
                r.z = v2 * v2;
                r.w = v3 * v3;
                __stcs(&y4[i4], r);
            }
        }
        // no trailing barrier: every next-row scratch write is preceded by
        // >=1 __syncthreads (B1 for buf/TMA, B2 for mred, B3+ for ired/ired2)
        // after this row's last read of the same slot.
    }
}

extern "C" void kernel_launch(void* const* d_in, const int* in_sizes, int n_in,
                              void* d_out, int out_size) {
    const float* X = (const float*)d_in[0];
    float* Y = (float*)d_out;

    static int n_sm = 0;
    if (n_sm == 0) {
        cudaDeviceGetAttribute(&n_sm, cudaDevAttrMultiProcessorCount, 0);
        cudaFuncSetAttribute(tsallis_secant_kernel,
                             cudaFuncAttributeMaxDynamicSharedMemorySize,
                             ROW_BYTES);
    }
    tsallis_secant_kernel<<<n_sm, THREADS, ROW_BYTES>>>(X, Y);
}